// round 15
// baseline (speedup 1.0000x reference)
#include <cuda_runtime.h>
#include <cuda_fp16.h>
#include <cstdint>
#include <math.h>

#define BQ 16
#define CC 128
#define LB 1024
#define LF 1024
#define RS 80                   // smem row stride (bytes) — conflict-free ldmatrix
#define TILEB (128 * RS)        // 10240 bytes per 128x32-f16 tile

// ---------------- device scratch ----------------
__device__ float g_sq4[BQ * LB * 4];             // per-(p, c-block) partial sums
__device__ float g_invn[BQ * LB];
__device__ float g_buf1[(size_t)BQ * LB * LF];   // GT
__device__ float g_buf2[(size_t)BQ * LB * LF];   // ST
__device__ __align__(16) __half g_Vh[(size_t)BQ * 16 * LF * CC];

__device__ __align__(16) __half g_bdT_h[(size_t)BQ * LB * CC];
__device__ __align__(16) __half g_bdT_l[(size_t)BQ * LB * CC];
__device__ __align__(16) __half g_fdT_h[(size_t)BQ * LB * CC];
__device__ __align__(16) __half g_fdT_l[(size_t)BQ * LB * CC];
__device__ __align__(16) __half g_bp[(size_t)BQ * 16 * CC * LB];
__device__ __align__(16) __half g_attT[(size_t)BQ * LF * LB];
__device__ __align__(16) __half g_yT[(size_t)BQ * 4096 * CC];
__device__ __align__(16) __half g_hT[(size_t)BQ * 4096 * CC];
__device__ __align__(16) __half g_W1p[CC * 1152];
__device__ __align__(16) __half g_W2p[CC * 1152];

// ---------------- asm helpers ----------------
__device__ __forceinline__ uint32_t s2u(const void* p) {
    uint32_t a;
    asm("{ .reg .u64 t; cvta.to.shared.u64 t, %1; cvt.u32.u64 %0, t; }" : "=r"(a) : "l"(p));
    return a;
}
__device__ __forceinline__ void cp16(uint32_t d, const void* s) {
    asm volatile("cp.async.cg.shared.global [%0], [%1], 16;" :: "r"(d), "l"(s));
}
__device__ __forceinline__ void cp16z(uint32_t d, const void* s, bool ok) {
    int sz = ok ? 16 : 0;
    asm volatile("cp.async.cg.shared.global [%0], [%1], 16, %2;" :: "r"(d), "l"(s), "r"(sz));
}
#define CP_COMMIT asm volatile("cp.async.commit_group;")
#define CP_WAIT1  asm volatile("cp.async.wait_group 1;")
#define CP_WAIT2  asm volatile("cp.async.wait_group 2;")

__device__ __forceinline__ void ldsm4(uint32_t* r, uint32_t a) {
    asm volatile("ldmatrix.sync.aligned.m8n8.x4.shared.b16 {%0,%1,%2,%3}, [%4];"
                 : "=r"(r[0]), "=r"(r[1]), "=r"(r[2]), "=r"(r[3]) : "r"(a));
}
__device__ __forceinline__ void mma16816(float* c, const uint32_t* a, const uint32_t* b) {
    asm volatile(
        "mma.sync.aligned.m16n8k16.row.col.f32.f16.f16.f32 "
        "{%0,%1,%2,%3}, {%4,%5,%6,%7}, {%8,%9}, {%0,%1,%2,%3};"
        : "+f"(c[0]), "+f"(c[1]), "+f"(c[2]), "+f"(c[3])
        : "r"(a[0]), "r"(a[1]), "r"(a[2]), "r"(a[3]), "r"(b[0]), "r"(b[1]));
}
__device__ __forceinline__ void split2h(float v, __half* ph, __half* pl) {
    __half h = __float2half_rn(v);
    *ph = h;
    *pl = __float2half_rn(v - __half2float(h));
}
__device__ __forceinline__ uint32_t a_addr(uint32_t tile, int m, int kk, int lane) {
    return tile + (m + (lane & 15)) * RS + (kk + ((lane >> 4) << 3)) * 2;
}
__device__ __forceinline__ uint32_t b_addr(uint32_t tile, int n, int kk, int lane) {
    return tile + (n + (lane & 7) + ((lane & 16) >> 1)) * RS + (kk + (lane & 8)) * 2;
}

__device__ __forceinline__ void mma_chunk1(uint32_t aT, uint32_t bT, int wm, int wn,
                                           int lane, float acc[4][4][4]) {
    #pragma unroll
    for (int kk = 0; kk < 32; kk += 16) {
        uint32_t a[4][4], bf[2][4];
        #pragma unroll
        for (int mi = 0; mi < 4; mi++) ldsm4(a[mi], a_addr(aT, wm + mi * 16, kk, lane));
        #pragma unroll
        for (int ni = 0; ni < 2; ni++) ldsm4(bf[ni], b_addr(bT, wn + ni * 16, kk, lane));
        #pragma unroll
        for (int mi = 0; mi < 4; mi++)
            #pragma unroll
            for (int nj = 0; nj < 4; nj++)
                mma16816(acc[mi][nj], a[mi], &bf[nj >> 1][(nj & 1) * 2]);
    }
}

__device__ __forceinline__ void mma_chunk3(uint32_t AhT, uint32_t AlT, uint32_t BhT,
                                           uint32_t BlT, int wm, int wn, int lane,
                                           float acc[4][4][4]) {
    #pragma unroll
    for (int kk = 0; kk < 32; kk += 16) {
        uint32_t ah[4][4], al[4][4], bh[2][4], bl[2][4];
        #pragma unroll
        for (int mi = 0; mi < 4; mi++) {
            ldsm4(ah[mi], a_addr(AhT, wm + mi * 16, kk, lane));
            ldsm4(al[mi], a_addr(AlT, wm + mi * 16, kk, lane));
        }
        #pragma unroll
        for (int ni = 0; ni < 2; ni++) {
            ldsm4(bh[ni], b_addr(BhT, wn + ni * 16, kk, lane));
            ldsm4(bl[ni], b_addr(BlT, wn + ni * 16, kk, lane));
        }
        #pragma unroll
        for (int mi = 0; mi < 4; mi++)
            #pragma unroll
            for (int nj = 0; nj < 4; nj++) {
                mma16816(acc[mi][nj], ah[mi], &bh[nj >> 1][(nj & 1) * 2]);
                mma16816(acc[mi][nj], ah[mi], &bl[nj >> 1][(nj & 1) * 2]);
                mma16816(acc[mi][nj], al[mi], &bh[nj >> 1][(nj & 1) * 2]);
            }
    }
}

// ---------------- pack / elementwise ----------------
// pack fd/bd -> [p][c] hi/lo via smem transpose; per-(p,c-block) sumsq partials
__global__ void k_pack_down(const float* __restrict__ f, const float* __restrict__ b) {
    __shared__ float tf[32][33], tb[32][33];
    int bi = blockIdx.z;
    int yb = blockIdx.x;
    int cb = blockIdx.y;
    int c0 = cb * 32;
    int lane = threadIdx.x & 31, w = threadIdx.x >> 5;
    for (int yy = w; yy < 32; yy += 8) {
        size_t src = ((size_t)(bi * CC + c0 + yy) * 64 + 2 * yb) * 64 + 2 * lane;
        tf[yy][lane] = f[src];
        tb[yy][lane] = b[src];
    }
    __syncthreads();
    for (int yy = w; yy < 32; yy += 8) {
        float bv = tb[lane][yy];
        size_t o = ((size_t)(bi * 1024 + yb * 32 + yy)) * 128 + c0 + lane;
        split2h(tf[lane][yy], &g_fdT_h[o], &g_fdT_l[o]);
        split2h(bv, &g_bdT_h[o], &g_bdT_l[o]);
        float sq = bv * bv;
        #pragma unroll
        for (int off = 16; off; off >>= 1) sq += __shfl_xor_sync(0xFFFFFFFFu, sq, off);
        if (lane == 0) g_sq4[(bi * 1024 + yb * 32 + yy) * 4 + cb] = sq;
    }
}

__global__ void k_norm2() {
    int bi = blockIdx.x, p = threadIdx.x;
    __shared__ float sq[LB];
    float4 s4 = *(const float4*)&g_sq4[(bi * LB + p) * 4];
    sq[p] = s4.x + s4.y + s4.z + s4.w;
    __syncthreads();
    int y = p >> 5, x = p & 31;
    float ns = 0.f;
    #pragma unroll
    for (int dy = -1; dy <= 1; dy++)
        #pragma unroll
        for (int dx = -1; dx <= 1; dx++) {
            int y2 = y + dy, x2 = x + dx;
            if ((unsigned)y2 < 32u && (unsigned)x2 < 32u) ns += sq[(y2 << 5) + x2];
        }
    float n = sqrtf(ns); if (n < 1e-4f) n = 1e-4f;
    g_invn[bi * LB + p] = 1.0f / n;
}

// Merged mid kernel: DRAM-heavy bshift/packW blocks FIRST (overlap the L2-heavy
// ST wave), then ST stencil blocks.
#define NB_BSH  2048
#define NB_PW   576
#define NB_ST   65536
__global__ __launch_bounds__(256) void k_mid(const float* __restrict__ b,
                                             const float* __restrict__ W1,
                                             const float* __restrict__ W2) {
    __shared__ float sm[64][65];
    int x = blockIdx.x;
    int tid = threadIdx.x;
    if (x < NB_BSH) {
        // smem-staged bshift pack (one block per (bi,c))
        int c = x & 127, bi = x >> 7;
        const float* src = b + (size_t)(bi * CC + c) * 4096;
        #pragma unroll
        for (int i = 0; i < 16; i++) {
            int u = i * 256 + tid;
            sm[u >> 6][u & 63] = src[u];
        }
        __syncthreads();
        __half* outb = g_bp + ((size_t)(bi * 16) * CC + c) * 1024;
        #pragma unroll
        for (int it = 0; it < 8; it++) {
            int u = it * 256 + tid;
            int tap = u >> 7, g8 = u & 127;
            int yb = g8 >> 2, xb8 = g8 & 3;
            int py = tap >> 2, px = tap & 3;
            int row = 2 * yb + py - 1;
            bool rowok = (unsigned)row < 64u;
            int r = rowok ? row : 0;
            int col0 = 16 * xb8 + px - 1;
            __half h[8];
            #pragma unroll
            for (int j = 0; j < 8; j++) {
                int col = col0 + 2 * j;
                float v = (rowok && (unsigned)col < 64u) ? sm[r][col] : 0.f;
                h[j] = __float2half_rn(v);
            }
            *(uint4*)&outb[(size_t)tap * CC * 1024 + g8 * 8] = *(uint4*)h;
        }
    } else if (x < NB_BSH + NB_PW) {
        int t = x - NB_BSH;
        int i = t * 256 + tid;
        if (i < CC * 1152) {
            int k = i % 1152, co = i / 1152;
            int tap = k >> 7, ci = k & 127;
            int src = (co * 128 + ci) * 9 + tap;
            g_W1p[i] = __float2half_rn(W1[src]);
            g_W2p[i] = __float2half_rn(W2[src]);
        }
    } else {
        // ST[pf][pb] = invn[pb] * 9-tap diag stencil of GT -> buf2
        int t = x - NB_BSH - NB_PW;
        int bi = t >> 12;
        int i = (t & 4095) * 256 + tid;
        int pb = i & 1023, pf = i >> 10;
        int yb = pb >> 5, xb = pb & 31, yf = pf >> 5, xf = pf & 31;
        const float* GT = g_buf1 + ((size_t)bi << 20);
        float s = 0.f;
        #pragma unroll
        for (int dy = -1; dy <= 1; dy++)
            #pragma unroll
            for (int dx = -1; dx <= 1; dx++) {
                int a = yb + dy, b2 = xb + dx, c = yf + dy, d = xf + dx;
                if ((unsigned)a < 32u && (unsigned)b2 < 32u && (unsigned)c < 32u && (unsigned)d < 32u)
                    s += GT[((c << 5) + d) * LB + (a << 5) + b2];
            }
        g_buf2[((size_t)bi << 20) + i] = s * g_invn[bi * LB + pb];
    }
}

// fuse2(fuse1(S)) for one lf-row + row softmax -> attT[lf][:] half
__global__ __launch_bounds__(256) void k_fuse_smT() {
    __shared__ float wred[8];
    int bi = blockIdx.y, lf = blockIdx.x;
    int tid = threadIdx.x;
    int lane = tid & 31, warp = tid >> 5;
    int lfT = ((lf & 31) << 5) + (lf >> 5);
    const float* ST = g_buf2 + ((size_t)bi << 20);
    float v[4];
    float m = -1e30f;
    #pragma unroll
    for (int rI = 0; rI < 4; rI++) {
        int lb = rI * 256 + tid;
        int lbT = ((lb & 31) << 5) + (lb >> 5);
        float s = 0.f;
        #pragma unroll
        for (int j = -1; j <= 1; j++) {
            int a = lbT + j, b2 = lfT + j;
            if ((unsigned)a < 1024u && (unsigned)b2 < 1024u) {
                int r = ((a & 31) << 5) + (a >> 5);
                int c = ((b2 & 31) << 5) + (b2 >> 5);
                #pragma unroll
                for (int k = -1; k <= 1; k++) {
                    int rr = r + k, cc = c + k;
                    if ((unsigned)rr < 1024u && (unsigned)cc < 1024u)
                        s += ST[cc * LB + rr];
                }
            }
        }
        v[rI] = 10.0f * s;
        m = fmaxf(m, v[rI]);
    }
    #pragma unroll
    for (int o = 16; o; o >>= 1) m = fmaxf(m, __shfl_xor_sync(0xFFFFFFFFu, m, o));
    if (lane == 0) wred[warp] = m;
    __syncthreads();
    m = wred[0];
    #pragma unroll
    for (int w = 1; w < 8; w++) m = fmaxf(m, wred[w]);
    __syncthreads();
    float sum = 0.f;
    #pragma unroll
    for (int rI = 0; rI < 4; rI++) { v[rI] = __expf(v[rI] - m); sum += v[rI]; }
    #pragma unroll
    for (int o = 16; o; o >>= 1) sum += __shfl_xor_sync(0xFFFFFFFFu, sum, o);
    if (lane == 0) wred[warp] = sum;
    __syncthreads();
    float tot = 0.f;
    #pragma unroll
    for (int w = 0; w < 8; w++) tot += wred[w];
    float inv = 1.0f / tot;
    __half* O = g_attT + (size_t)(bi * LF + lf) * 1024;
    #pragma unroll
    for (int rI = 0; rI < 4; rI++) O[rI * 256 + tid] = __float2half_rn(v[rI] * inv);
}

// combine V(half) -> yT[pix][c] (half), 2 channels per thread
__global__ void k_comb_pack() {
    size_t i = (size_t)blockIdx.x * 256 + threadIdx.x;
    if (i >= (size_t)BQ * 4096 * 64) return;
    int c2 = (int)(i & 63) * 2;
    int pix = (int)(i >> 6) & 4095;
    int bi = (int)(i >> 18);
    int oy = pix >> 6, ox = pix & 63;
    int my = oy >> 1, mx = ox >> 1;
    int yfv[2], pyv[2], xfv[2], pxv[2];
    if (oy & 1) { yfv[0] = my; pyv[0] = 2; yfv[1] = my + 1; pyv[1] = 0; }
    else        { yfv[0] = my; pyv[0] = 1; yfv[1] = my - 1; pyv[1] = 3; }
    if (ox & 1) { xfv[0] = mx; pxv[0] = 2; xfv[1] = mx + 1; pxv[1] = 0; }
    else        { xfv[0] = mx; pxv[0] = 1; xfv[1] = mx - 1; pxv[1] = 3; }
    float s0 = 0.f, s1 = 0.f;
    #pragma unroll
    for (int a = 0; a < 2; a++) {
        if ((unsigned)yfv[a] >= 32u) continue;
        #pragma unroll
        for (int b2 = 0; b2 < 2; b2++) {
            if ((unsigned)xfv[b2] >= 32u) continue;
            int tap = pyv[a] * 4 + pxv[b2];
            int lf = yfv[a] * 32 + xfv[b2];
            __half2 hv = *(const __half2*)&g_Vh[((size_t)(bi * 16 + tap) * LF + lf) * CC + c2];
            float2 fv = __half22float2(hv);
            s0 += fv.x; s1 += fv.y;
        }
    }
    *(__half2*)&g_yT[((size_t)bi * 4096 + pix) * CC + c2] =
        __halves2half2(__float2half_rn(0.25f * s0), __float2half_rn(0.25f * s1));
}

// ---------------- mma GEMM kernels ----------------
// GT = fdT(split) @ bdT(split)^T, K=128 (4 chunks, 3-pass), 2-stage, 2 blocks/SM
__global__ __launch_bounds__(256, 2) void k_mmaG() {
    extern __shared__ char smc[];
    uint32_t sb = s2u(smc);
    int tid = threadIdx.x, lane = tid & 31, warp = tid >> 5;
    int bi = blockIdx.z, m0 = blockIdx.y * 128, n0 = blockIdx.x * 128;
    int wm = (warp >> 2) * 64, wn = (warp & 3) * 32;
    const char* srcs[4] = {
        (const char*)g_fdT_h + (size_t)(bi * LB + m0) * 256,
        (const char*)g_fdT_l + (size_t)(bi * LB + m0) * 256,
        (const char*)g_bdT_h + (size_t)(bi * LB + n0) * 256,
        (const char*)g_bdT_l + (size_t)(bi * LB + n0) * 256};
    float acc[4][4][4] = {};
    auto stage = [&](int ch, int s) {
        for (int u = tid; u < 2048; u += 256) {
            int t = u >> 9, idx = u & 511, r = idx >> 2, c4 = idx & 3;
            cp16(sb + (s * 4 + t) * TILEB + r * RS + c4 * 16,
                 srcs[t] + (size_t)r * 256 + ch * 64 + c4 * 16);
        }
    };
    stage(0, 0); CP_COMMIT;
    for (int i = 0; i < 4; i++) {
        if (i + 1 < 4) { stage(i + 1, (i + 1) & 1); CP_COMMIT; CP_WAIT1; }
        else { asm volatile("cp.async.wait_group 0;"); }
        __syncthreads();
        uint32_t base = sb + (i & 1) * 4 * TILEB;
        mma_chunk3(base, base + TILEB, base + 2 * TILEB, base + 3 * TILEB, wm, wn, lane, acc);
        __syncthreads();
    }
    float* out = g_buf1 + ((size_t)bi << 20);
    #pragma unroll
    for (int mi = 0; mi < 4; mi++)
        #pragma unroll
        for (int nj = 0; nj < 4; nj++) {
            int grow = m0 + wm + mi * 16 + (lane >> 2);
            int gcol = n0 + wn + nj * 8 + (lane & 3) * 2;
            *(float2*)&out[(size_t)grow * LB + gcol] = make_float2(acc[mi][nj][0], acc[mi][nj][1]);
            *(float2*)&out[(size_t)(grow + 8) * LB + gcol] = make_float2(acc[mi][nj][2], acc[mi][nj][3]);
        }
}

// V[tap][lf][c] = attT.bp, M=128, K=1024 (32 chunks, 4-stage), 2 blocks/SM
__global__ __launch_bounds__(256, 2) void k_mmaV() {
    extern __shared__ char smc[];
    uint32_t sb = s2u(smc);
    int tid = threadIdx.x, lane = tid & 31, warp = tid >> 5;
    int bi = blockIdx.z, tap = blockIdx.y, m0 = blockIdx.x * 128;
    int wm = (warp >> 2) * 64, wn = (warp & 3) * 32;
    const char* srcA = (const char*)g_attT + (size_t)(bi * LF + m0) * 2048;
    const char* srcB = (const char*)g_bp + (size_t)((bi * 16 + tap) * CC) * 2048;
    float acc[4][4][4] = {};
    const int NC = 32;
    auto stage = [&](int ch, int s) {
        for (int u = tid; u < 1024; u += 256) {
            int t = u >> 9, idx = u & 511, r = idx >> 2, c4 = idx & 3;
            cp16(sb + (s * 2 + t) * TILEB + r * RS + c4 * 16,
                 (t ? srcB : srcA) + (size_t)r * 2048 + ch * 64 + c4 * 16);
        }
    };
    stage(0, 0); CP_COMMIT;
    stage(1, 1); CP_COMMIT;
    stage(2, 2); CP_COMMIT;
    for (int i = 0; i < NC; i++) {
        CP_WAIT2;
        __syncthreads();
        if (i + 3 < NC) stage(i + 3, (i + 3) & 3);
        CP_COMMIT;
        uint32_t base = sb + (i & 3) * 2 * TILEB;
        mma_chunk1(base, base + TILEB, wm, wn, lane, acc);
    }
    __half* out = g_Vh + (size_t)(bi * 16 + tap) * LF * CC;
    #pragma unroll
    for (int mi = 0; mi < 4; mi++)
        #pragma unroll
        for (int nj = 0; nj < 4; nj++) {
            int glf = m0 + wm + mi * 16 + (lane >> 2);
            int gc = wn + nj * 8 + (lane & 3) * 2;
            *(__half2*)&out[(size_t)glf * CC + gc] =
                __halves2half2(__float2half_rn(acc[mi][nj][0]), __float2half_rn(acc[mi][nj][1]));
            *(__half2*)&out[(size_t)(glf + 8) * CC + gc] =
                __halves2half2(__float2half_rn(acc[mi][nj][2]), __float2half_rn(acc[mi][nj][3]));
        }
}

// conv3x3 implicit GEMM: K=1152 (36 chunks, 4-stage), 2 blocks/SM
__global__ __launch_bounds__(256, 2) void k_mmaConv(
    const __half* __restrict__ X, const __half* __restrict__ Wp,
    const float* __restrict__ bias, float* __restrict__ fout, int mode) {
    extern __shared__ char smc[];
    uint32_t sb = s2u(smc);
    int tid = threadIdx.x, lane = tid & 31, warp = tid >> 5;
    int bi = blockIdx.z, n0 = blockIdx.x * 128;
    int wm = (warp >> 2) * 64, wn = (warp & 3) * 32;
    const char* Xb = (const char*)X + (size_t)bi * 4096 * 256;
    const char* Wb = (const char*)Wp;
    float acc[4][4][4] = {};
    const int NC = 36;
    auto stage = [&](int ch, int s) {
        int tap = ch >> 2, ci0 = (ch & 3) * 32;
        int ky = tap / 3 - 1, kx = tap % 3 - 1;
        for (int u = tid; u < 1024; u += 256) {
            int t = u >> 9, idx = u & 511, r = idx >> 2, c4 = idx & 3;
            uint32_t dst = sb + (s * 2 + t) * TILEB + r * RS + c4 * 16;
            if (t) {
                cp16(dst, Wb + (size_t)r * 2304 + (tap * 128 + ci0) * 2 + c4 * 16);
            } else {
                int p = n0 + r;
                int sy = (p >> 6) + ky, sx = (p & 63) + kx;
                bool ok = (unsigned)sy < 64u && (unsigned)sx < 64u;
                int sp = ok ? sy * 64 + sx : 0;
                cp16z(dst, Xb + (size_t)sp * 256 + ci0 * 2 + c4 * 16, ok);
            }
        }
    };
    stage(0, 0); CP_COMMIT;
    stage(1, 1); CP_COMMIT;
    stage(2, 2); CP_COMMIT;
    for (int i = 0; i < NC; i++) {
        CP_WAIT2;
        __syncthreads();
        if (i + 3 < NC) stage(i + 3, (i + 3) & 3);
        CP_COMMIT;
        uint32_t base = sb + (i & 3) * 2 * TILEB;
        mma_chunk1(base, base + TILEB, wm, wn, lane, acc);
    }
    if (mode == 0) {
        #pragma unroll
        for (int mi = 0; mi < 4; mi++)
            #pragma unroll
            for (int nj = 0; nj < 4; nj++) {
                int pr = wm + mi * 16 + (lane >> 2);
                int col = wn + nj * 8 + (lane & 3) * 2;
                float b0 = bias[col], b1 = bias[col + 1];
                float v0 = acc[mi][nj][0] + b0, v1 = acc[mi][nj][1] + b1;
                float v2 = acc[mi][nj][2] + b0, v3 = acc[mi][nj][3] + b1;
                v0 = v0 > 0.f ? v0 : (__expf(v0) - 1.0f);
                v1 = v1 > 0.f ? v1 : (__expf(v1) - 1.0f);
                v2 = v2 > 0.f ? v2 : (__expf(v2) - 1.0f);
                v3 = v3 > 0.f ? v3 : (__expf(v3) - 1.0f);
                __half2* o0 = (__half2*)&g_hT[((size_t)bi * 4096 + n0 + pr) * 128 + col];
                __half2* o1 = (__half2*)&g_hT[((size_t)bi * 4096 + n0 + pr + 8) * 128 + col];
                *o0 = __halves2half2(__float2half_rn(v0), __float2half_rn(v1));
                *o1 = __halves2half2(__float2half_rn(v2), __float2half_rn(v3));
            }
    } else {
        __syncthreads();
        float* sd = (float*)smc;
        #pragma unroll
        for (int mi = 0; mi < 4; mi++)
            #pragma unroll
            for (int nj = 0; nj < 4; nj++) {
                int pr = wm + mi * 16 + (lane >> 2);
                int col = wn + nj * 8 + (lane & 3) * 2;
                float b0 = bias[col], b1 = bias[col + 1];
                float v0 = acc[mi][nj][0] + b0, v1 = acc[mi][nj][1] + b1;
                float v2 = acc[mi][nj][2] + b0, v3 = acc[mi][nj][3] + b1;
                sd[pr * 129 + col] = v0 > 0.f ? v0 : (__expf(v0) - 1.0f);
                sd[pr * 129 + col + 1] = v1 > 0.f ? v1 : (__expf(v1) - 1.0f);
                sd[(pr + 8) * 129 + col] = v2 > 0.f ? v2 : (__expf(v2) - 1.0f);
                sd[(pr + 8) * 129 + col + 1] = v3 > 0.f ? v3 : (__expf(v3) - 1.0f);
            }
        __syncthreads();
        for (int u = tid; u < 16384; u += 256) {
            int pix = u & 127, co = u >> 7;
            fout[((size_t)bi * 128 + co) * 4096 + n0 + pix] = sd[pix * 129 + co];
        }
    }
}

// ---------------------------------------------------------------------------
extern "C" void kernel_launch(void* const* d_in, const int* in_sizes, int n_in,
                              void* d_out, int out_size) {
    const float* f  = (const float*)d_in[0];
    const float* b  = (const float*)d_in[1];
    const float* W1 = (const float*)d_in[2];
    const float* b1 = (const float*)d_in[3];
    const float* W2 = (const float*)d_in[4];
    const float* b2 = (const float*)d_in[5];
    float* out = (float*)d_out;

    cudaFuncSetAttribute(k_mmaG, cudaFuncAttributeMaxDynamicSharedMemorySize, 8 * TILEB);
    cudaFuncSetAttribute(k_mmaV, cudaFuncAttributeMaxDynamicSharedMemorySize, 8 * TILEB);
    cudaFuncSetAttribute(k_mmaConv, cudaFuncAttributeMaxDynamicSharedMemorySize, 82944);

    __half *yh, *hh, *w1p, *w2p;
    cudaGetSymbolAddress((void**)&yh, g_yT);
    cudaGetSymbolAddress((void**)&hh, g_hT);
    cudaGetSymbolAddress((void**)&w1p, g_W1p);
    cudaGetSymbolAddress((void**)&w2p, g_W2p);

    k_pack_down<<<dim3(32, 4, BQ), 256>>>(f, b);
    k_norm2<<<BQ, 1024>>>();

    k_mmaG<<<dim3(8, 8, BQ), 256, 8 * TILEB>>>();
    k_mid<<<NB_BSH + NB_PW + NB_ST, 256>>>(b, W1, W2);
    k_fuse_smT<<<dim3(1024, BQ), 256>>>();

    k_mmaV<<<dim3(8, 16, BQ), 256, 8 * TILEB>>>();
    k_comb_pack<<<(int)(((size_t)BQ * 4096 * 64 + 255) / 256), 256>>>();

    k_mmaConv<<<dim3(32, 1, BQ), 256, 82944>>>(yh, w1p, b1, nullptr, 0);
    k_mmaConv<<<dim3(32, 1, BQ), 256, 82944>>>(hh, w2p, b2, out, 1);

    (void)in_sizes; (void)n_in; (void)out_size;
}

// round 16
// speedup vs baseline: 1.0384x; 1.0384x over previous
#include <cuda_runtime.h>
#include <cuda_fp16.h>
#include <cstdint>
#include <math.h>

#define BQ 16
#define CC 128
#define LB 1024
#define LF 1024
#define RS 80                   // smem row stride (bytes) — conflict-free ldmatrix
#define TILEB (128 * RS)        // 10240 bytes per 128x32-f16 tile

// ---------------- device scratch ----------------
__device__ float g_sq[BQ * LB];
__device__ float g_invn[BQ * LB];
__device__ float g_buf1[(size_t)BQ * LB * LF];   // GT
__device__ float g_buf2[(size_t)BQ * LB * LF];   // ST
__device__ __align__(16) __half g_Vh[(size_t)BQ * 16 * LF * CC];

__device__ __align__(16) __half g_bdT_h[(size_t)BQ * LB * CC];
__device__ __align__(16) __half g_bdT_l[(size_t)BQ * LB * CC];
__device__ __align__(16) __half g_fdT_h[(size_t)BQ * LB * CC];
__device__ __align__(16) __half g_fdT_l[(size_t)BQ * LB * CC];
__device__ __align__(16) __half g_bp[(size_t)BQ * 16 * CC * LB];
__device__ __align__(16) __half g_attT[(size_t)BQ * LF * LB];
__device__ __align__(16) __half g_yT[(size_t)BQ * 4096 * CC];
__device__ __align__(16) __half g_hT[(size_t)BQ * 4096 * CC];
__device__ __align__(16) __half g_W1p[CC * 1152];
__device__ __align__(16) __half g_W2p[CC * 1152];

// ---------------- asm helpers ----------------
__device__ __forceinline__ uint32_t s2u(const void* p) {
    uint32_t a;
    asm("{ .reg .u64 t; cvta.to.shared.u64 t, %1; cvt.u32.u64 %0, t; }" : "=r"(a) : "l"(p));
    return a;
}
__device__ __forceinline__ void cp16(uint32_t d, const void* s) {
    asm volatile("cp.async.cg.shared.global [%0], [%1], 16;" :: "r"(d), "l"(s));
}
__device__ __forceinline__ void cp16z(uint32_t d, const void* s, bool ok) {
    int sz = ok ? 16 : 0;
    asm volatile("cp.async.cg.shared.global [%0], [%1], 16, %2;" :: "r"(d), "l"(s), "r"(sz));
}
#define CP_COMMIT asm volatile("cp.async.commit_group;")
#define CP_WAIT1  asm volatile("cp.async.wait_group 1;")
#define CP_WAIT2  asm volatile("cp.async.wait_group 2;")

__device__ __forceinline__ void ldsm4(uint32_t* r, uint32_t a) {
    asm volatile("ldmatrix.sync.aligned.m8n8.x4.shared.b16 {%0,%1,%2,%3}, [%4];"
                 : "=r"(r[0]), "=r"(r[1]), "=r"(r[2]), "=r"(r[3]) : "r"(a));
}
__device__ __forceinline__ void mma16816(float* c, const uint32_t* a, const uint32_t* b) {
    asm volatile(
        "mma.sync.aligned.m16n8k16.row.col.f32.f16.f16.f32 "
        "{%0,%1,%2,%3}, {%4,%5,%6,%7}, {%8,%9}, {%0,%1,%2,%3};"
        : "+f"(c[0]), "+f"(c[1]), "+f"(c[2]), "+f"(c[3])
        : "r"(a[0]), "r"(a[1]), "r"(a[2]), "r"(a[3]), "r"(b[0]), "r"(b[1]));
}
__device__ __forceinline__ void split2h(float v, __half* ph, __half* pl) {
    __half h = __float2half_rn(v);
    *ph = h;
    *pl = __float2half_rn(v - __half2float(h));
}
__device__ __forceinline__ uint32_t a_addr(uint32_t tile, int m, int kk, int lane) {
    return tile + (m + (lane & 15)) * RS + (kk + ((lane >> 4) << 3)) * 2;
}
__device__ __forceinline__ uint32_t b_addr(uint32_t tile, int n, int kk, int lane) {
    return tile + (n + (lane & 7) + ((lane & 16) >> 1)) * RS + (kk + (lane & 8)) * 2;
}

__device__ __forceinline__ void mma_chunk1(uint32_t aT, uint32_t bT, int wm, int wn,
                                           int lane, float acc[4][4][4]) {
    #pragma unroll
    for (int kk = 0; kk < 32; kk += 16) {
        uint32_t a[4][4], bf[2][4];
        #pragma unroll
        for (int mi = 0; mi < 4; mi++) ldsm4(a[mi], a_addr(aT, wm + mi * 16, kk, lane));
        #pragma unroll
        for (int ni = 0; ni < 2; ni++) ldsm4(bf[ni], b_addr(bT, wn + ni * 16, kk, lane));
        #pragma unroll
        for (int mi = 0; mi < 4; mi++)
            #pragma unroll
            for (int nj = 0; nj < 4; nj++)
                mma16816(acc[mi][nj], a[mi], &bf[nj >> 1][(nj & 1) * 2]);
    }
}

__device__ __forceinline__ void mma_chunk3(uint32_t AhT, uint32_t AlT, uint32_t BhT,
                                           uint32_t BlT, int wm, int wn, int lane,
                                           float acc[4][4][4]) {
    #pragma unroll
    for (int kk = 0; kk < 32; kk += 16) {
        uint32_t ah[4][4], al[4][4], bh[2][4], bl[2][4];
        #pragma unroll
        for (int mi = 0; mi < 4; mi++) {
            ldsm4(ah[mi], a_addr(AhT, wm + mi * 16, kk, lane));
            ldsm4(al[mi], a_addr(AlT, wm + mi * 16, kk, lane));
        }
        #pragma unroll
        for (int ni = 0; ni < 2; ni++) {
            ldsm4(bh[ni], b_addr(BhT, wn + ni * 16, kk, lane));
            ldsm4(bl[ni], b_addr(BlT, wn + ni * 16, kk, lane));
        }
        #pragma unroll
        for (int mi = 0; mi < 4; mi++)
            #pragma unroll
            for (int nj = 0; nj < 4; nj++) {
                mma16816(acc[mi][nj], ah[mi], &bh[nj >> 1][(nj & 1) * 2]);
                mma16816(acc[mi][nj], ah[mi], &bl[nj >> 1][(nj & 1) * 2]);
                mma16816(acc[mi][nj], al[mi], &bh[nj >> 1][(nj & 1) * 2]);
            }
    }
}

// ---------------- pack / elementwise ----------------
__global__ void k_zero_sq() {
    int i = blockIdx.x * 256 + threadIdx.x;
    if (i < BQ * LB) g_sq[i] = 0.f;
}

// pack fd/bd -> [p][c] hi/lo via smem transpose; also accumulate bd sumsq per p
__global__ void k_pack_down(const float* __restrict__ f, const float* __restrict__ b) {
    __shared__ float tf[32][33], tb[32][33];
    int bi = blockIdx.z;
    int yb = blockIdx.x;
    int c0 = blockIdx.y * 32;
    int lane = threadIdx.x & 31, w = threadIdx.x >> 5;
    for (int yy = w; yy < 32; yy += 8) {
        size_t src = ((size_t)(bi * CC + c0 + yy) * 64 + 2 * yb) * 64 + 2 * lane;
        tf[yy][lane] = f[src];
        tb[yy][lane] = b[src];
    }
    __syncthreads();
    for (int yy = w; yy < 32; yy += 8) {
        float bv = tb[lane][yy];
        size_t o = ((size_t)(bi * 1024 + yb * 32 + yy)) * 128 + c0 + lane;
        split2h(tf[lane][yy], &g_fdT_h[o], &g_fdT_l[o]);
        split2h(bv, &g_bdT_h[o], &g_bdT_l[o]);
        float sq = bv * bv;
        #pragma unroll
        for (int off = 16; off; off >>= 1) sq += __shfl_xor_sync(0xFFFFFFFFu, sq, off);
        if (lane == 0) atomicAdd(&g_sq[bi * 1024 + yb * 32 + yy], sq);
    }
}

__global__ void k_norm2() {
    int bi = blockIdx.x, p = threadIdx.x;
    __shared__ float sq[LB];
    sq[p] = g_sq[bi * LB + p];
    __syncthreads();
    int y = p >> 5, x = p & 31;
    float ns = 0.f;
    #pragma unroll
    for (int dy = -1; dy <= 1; dy++)
        #pragma unroll
        for (int dx = -1; dx <= 1; dx++) {
            int y2 = y + dy, x2 = x + dx;
            if ((unsigned)y2 < 32u && (unsigned)x2 < 32u) ns += sq[(y2 << 5) + x2];
        }
    float n = sqrtf(ns); if (n < 1e-4f) n = 1e-4f;
    g_invn[bi * LB + p] = 1.0f / n;
}

// Merged mid kernel: ST stencil (diagonal-offset form, 4 outputs/thread),
// then bshift pack, then W pack.
#define NB_ST   16384
#define NB_BSH  2048
#define NB_PW   576
__global__ __launch_bounds__(256) void k_mid(const float* __restrict__ b,
                                             const float* __restrict__ W1,
                                             const float* __restrict__ W2) {
    __shared__ float sm[64][65];
    int x = blockIdx.x;
    int tid = threadIdx.x;
    if (x < NB_ST) {
        // ST[pf][pb] = invn[pb] * 9-tap diag stencil of GT.
        // Tap (dy,dx) address offset from base = (32*dy+dx)*(LB+1); validity
        // separates into row(dy) and col(dx) flags.
        int bi = x >> 10;
        const float* GT = g_buf1 + ((size_t)bi << 20);
        float* OUT = g_buf2 + ((size_t)bi << 20);
        const float* INV = g_invn + bi * LB;
        int ibase = (x & 1023) * 1024 + tid;
        #pragma unroll
        for (int j = 0; j < 4; j++) {
            int i = ibase + j * 256;
            int pb = i & 1023, pf = i >> 10;
            int yb = pb >> 5, xb = pb & 31, yf = pf >> 5, xf = pf & 31;
            bool rm = (yb > 0) && (yf > 0);
            bool rp = (yb < 31) && (yf < 31);
            bool cm = (xb > 0) && (xf > 0);
            bool cp = (xb < 31) && (xf < 31);
            const float* base = GT + (size_t)pf * LB + pb;
            float s = base[0];
            if (cm) s += base[-1025];
            if (cp) s += base[1025];
            if (rm) {
                s += base[-32 * 1025];
                if (cm) s += base[-33 * 1025];
                if (cp) s += base[-31 * 1025];
            }
            if (rp) {
                s += base[32 * 1025];
                if (cm) s += base[31 * 1025];
                if (cp) s += base[33 * 1025];
            }
            OUT[i] = s * INV[pb];
        }
    } else if (x < NB_ST + NB_BSH) {
        // smem-staged bshift pack (one block per (bi,c))
        int t = x - NB_ST;
        int c = t & 127, bi = t >> 7;
        const float* src = b + (size_t)(bi * CC + c) * 4096;
        #pragma unroll
        for (int i = 0; i < 16; i++) {
            int u = i * 256 + tid;
            sm[u >> 6][u & 63] = src[u];
        }
        __syncthreads();
        __half* outb = g_bp + ((size_t)(bi * 16) * CC + c) * 1024;
        #pragma unroll
        for (int it = 0; it < 8; it++) {
            int u = it * 256 + tid;
            int tap = u >> 7, g8 = u & 127;
            int yb = g8 >> 2, xb8 = g8 & 3;
            int py = tap >> 2, px = tap & 3;
            int row = 2 * yb + py - 1;
            bool rowok = (unsigned)row < 64u;
            int r = rowok ? row : 0;
            int col0 = 16 * xb8 + px - 1;
            __half h[8];
            #pragma unroll
            for (int j = 0; j < 8; j++) {
                int col = col0 + 2 * j;
                float v = (rowok && (unsigned)col < 64u) ? sm[r][col] : 0.f;
                h[j] = __float2half_rn(v);
            }
            *(uint4*)&outb[(size_t)tap * CC * 1024 + g8 * 8] = *(uint4*)h;
        }
    } else {
        int t = x - NB_ST - NB_BSH;
        int i = t * 256 + tid;
        if (i < CC * 1152) {
            int k = i % 1152, co = i / 1152;
            int tap = k >> 7, ci = k & 127;
            int src = (co * 128 + ci) * 9 + tap;
            g_W1p[i] = __float2half_rn(W1[src]);
            g_W2p[i] = __float2half_rn(W2[src]);
        }
    }
}

// fuse2(fuse1(S)) for one lf-row + row softmax -> attT[lf][:] half
__global__ __launch_bounds__(256) void k_fuse_smT() {
    __shared__ float red[256];
    int bi = blockIdx.y, lf = blockIdx.x;
    int tid = threadIdx.x;
    int lfT = ((lf & 31) << 5) + (lf >> 5);
    const float* ST = g_buf2 + ((size_t)bi << 20);
    float v[4];
    float m = -1e30f;
    #pragma unroll
    for (int rI = 0; rI < 4; rI++) {
        int lb = rI * 256 + tid;
        int lbT = ((lb & 31) << 5) + (lb >> 5);
        float s = 0.f;
        #pragma unroll
        for (int j = -1; j <= 1; j++) {
            int a = lbT + j, b2 = lfT + j;
            if ((unsigned)a < 1024u && (unsigned)b2 < 1024u) {
                int r = ((a & 31) << 5) + (a >> 5);
                int c = ((b2 & 31) << 5) + (b2 >> 5);
                #pragma unroll
                for (int k = -1; k <= 1; k++) {
                    int rr = r + k, cc = c + k;
                    if ((unsigned)rr < 1024u && (unsigned)cc < 1024u)
                        s += ST[cc * LB + rr];
                }
            }
        }
        v[rI] = 10.0f * s;
        m = fmaxf(m, v[rI]);
    }
    red[tid] = m;
    __syncthreads();
    for (int s2 = 128; s2; s2 >>= 1) {
        if (tid < s2) red[tid] = fmaxf(red[tid], red[tid + s2]);
        __syncthreads();
    }
    m = red[0];
    __syncthreads();
    float sum = 0.f;
    #pragma unroll
    for (int rI = 0; rI < 4; rI++) { v[rI] = __expf(v[rI] - m); sum += v[rI]; }
    red[tid] = sum;
    __syncthreads();
    for (int s2 = 128; s2; s2 >>= 1) {
        if (tid < s2) red[tid] += red[tid + s2];
        __syncthreads();
    }
    float inv = 1.0f / red[0];
    __half* O = g_attT + (size_t)(bi * LF + lf) * 1024;
    #pragma unroll
    for (int rI = 0; rI < 4; rI++) O[rI * 256 + tid] = __float2half_rn(v[rI] * inv);
}

// combine V(half) -> yT[pix][c] (half), 2 channels per thread
__global__ void k_comb_pack() {
    size_t i = (size_t)blockIdx.x * 256 + threadIdx.x;
    if (i >= (size_t)BQ * 4096 * 64) return;
    int c2 = (int)(i & 63) * 2;
    int pix = (int)(i >> 6) & 4095;
    int bi = (int)(i >> 18);
    int oy = pix >> 6, ox = pix & 63;
    int my = oy >> 1, mx = ox >> 1;
    int yfv[2], pyv[2], xfv[2], pxv[2];
    if (oy & 1) { yfv[0] = my; pyv[0] = 2; yfv[1] = my + 1; pyv[1] = 0; }
    else        { yfv[0] = my; pyv[0] = 1; yfv[1] = my - 1; pyv[1] = 3; }
    if (ox & 1) { xfv[0] = mx; pxv[0] = 2; xfv[1] = mx + 1; pxv[1] = 0; }
    else        { xfv[0] = mx; pxv[0] = 1; xfv[1] = mx - 1; pxv[1] = 3; }
    float s0 = 0.f, s1 = 0.f;
    #pragma unroll
    for (int a = 0; a < 2; a++) {
        if ((unsigned)yfv[a] >= 32u) continue;
        #pragma unroll
        for (int b2 = 0; b2 < 2; b2++) {
            if ((unsigned)xfv[b2] >= 32u) continue;
            int tap = pyv[a] * 4 + pxv[b2];
            int lf = yfv[a] * 32 + xfv[b2];
            __half2 hv = *(const __half2*)&g_Vh[((size_t)(bi * 16 + tap) * LF + lf) * CC + c2];
            float2 fv = __half22float2(hv);
            s0 += fv.x; s1 += fv.y;
        }
    }
    *(__half2*)&g_yT[((size_t)bi * 4096 + pix) * CC + c2] =
        __halves2half2(__float2half_rn(0.25f * s0), __float2half_rn(0.25f * s1));
}

// ---------------- mma GEMM kernels ----------------
// GT = fdT(split) @ bdT(split)^T, K=128 (4 chunks, 3-pass), 2-stage, 2 blocks/SM
__global__ __launch_bounds__(256, 2) void k_mmaG() {
    extern __shared__ char smc[];
    uint32_t sb = s2u(smc);
    int tid = threadIdx.x, lane = tid & 31, warp = tid >> 5;
    int bi = blockIdx.z, m0 = blockIdx.y * 128, n0 = blockIdx.x * 128;
    int wm = (warp >> 2) * 64, wn = (warp & 3) * 32;
    const char* srcs[4] = {
        (const char*)g_fdT_h + (size_t)(bi * LB + m0) * 256,
        (const char*)g_fdT_l + (size_t)(bi * LB + m0) * 256,
        (const char*)g_bdT_h + (size_t)(bi * LB + n0) * 256,
        (const char*)g_bdT_l + (size_t)(bi * LB + n0) * 256};
    float acc[4][4][4] = {};
    auto stage = [&](int ch, int s) {
        for (int u = tid; u < 2048; u += 256) {
            int t = u >> 9, idx = u & 511, r = idx >> 2, c4 = idx & 3;
            cp16(sb + (s * 4 + t) * TILEB + r * RS + c4 * 16,
                 srcs[t] + (size_t)r * 256 + ch * 64 + c4 * 16);
        }
    };
    stage(0, 0); CP_COMMIT;
    for (int i = 0; i < 4; i++) {
        if (i + 1 < 4) { stage(i + 1, (i + 1) & 1); CP_COMMIT; CP_WAIT1; }
        else { asm volatile("cp.async.wait_group 0;"); }
        __syncthreads();
        uint32_t base = sb + (i & 1) * 4 * TILEB;
        mma_chunk3(base, base + TILEB, base + 2 * TILEB, base + 3 * TILEB, wm, wn, lane, acc);
        __syncthreads();
    }
    float* out = g_buf1 + ((size_t)bi << 20);
    #pragma unroll
    for (int mi = 0; mi < 4; mi++)
        #pragma unroll
        for (int nj = 0; nj < 4; nj++) {
            int grow = m0 + wm + mi * 16 + (lane >> 2);
            int gcol = n0 + wn + nj * 8 + (lane & 3) * 2;
            *(float2*)&out[(size_t)grow * LB + gcol] = make_float2(acc[mi][nj][0], acc[mi][nj][1]);
            *(float2*)&out[(size_t)(grow + 8) * LB + gcol] = make_float2(acc[mi][nj][2], acc[mi][nj][3]);
        }
}

// V[tap][lf][c] = attT.bp, M=128, K=1024 (32 chunks, 4-stage), 2 blocks/SM
__global__ __launch_bounds__(256, 2) void k_mmaV() {
    extern __shared__ char smc[];
    uint32_t sb = s2u(smc);
    int tid = threadIdx.x, lane = tid & 31, warp = tid >> 5;
    int bi = blockIdx.z, tap = blockIdx.y, m0 = blockIdx.x * 128;
    int wm = (warp >> 2) * 64, wn = (warp & 3) * 32;
    const char* srcA = (const char*)g_attT + (size_t)(bi * LF + m0) * 2048;
    const char* srcB = (const char*)g_bp + (size_t)((bi * 16 + tap) * CC) * 2048;
    float acc[4][4][4] = {};
    const int NC = 32;
    auto stage = [&](int ch, int s) {
        for (int u = tid; u < 1024; u += 256) {
            int t = u >> 9, idx = u & 511, r = idx >> 2, c4 = idx & 3;
            cp16(sb + (s * 2 + t) * TILEB + r * RS + c4 * 16,
                 (t ? srcB : srcA) + (size_t)r * 2048 + ch * 64 + c4 * 16);
        }
    };
    stage(0, 0); CP_COMMIT;
    stage(1, 1); CP_COMMIT;
    stage(2, 2); CP_COMMIT;
    for (int i = 0; i < NC; i++) {
        CP_WAIT2;
        __syncthreads();
        if (i + 3 < NC) stage(i + 3, (i + 3) & 3);
        CP_COMMIT;
        uint32_t base = sb + (i & 3) * 2 * TILEB;
        mma_chunk1(base, base + TILEB, wm, wn, lane, acc);
    }
    __half* out = g_Vh + (size_t)(bi * 16 + tap) * LF * CC;
    #pragma unroll
    for (int mi = 0; mi < 4; mi++)
        #pragma unroll
        for (int nj = 0; nj < 4; nj++) {
            int glf = m0 + wm + mi * 16 + (lane >> 2);
            int gc = wn + nj * 8 + (lane & 3) * 2;
            *(__half2*)&out[(size_t)glf * CC + gc] =
                __halves2half2(__float2half_rn(acc[mi][nj][0]), __float2half_rn(acc[mi][nj][1]));
            *(__half2*)&out[(size_t)(glf + 8) * CC + gc] =
                __halves2half2(__float2half_rn(acc[mi][nj][2]), __float2half_rn(acc[mi][nj][3]));
        }
}

// conv3x3 implicit GEMM: K=1152 (36 chunks, 4-stage), 2 blocks/SM
__global__ __launch_bounds__(256, 2) void k_mmaConv(
    const __half* __restrict__ X, const __half* __restrict__ Wp,
    const float* __restrict__ bias, float* __restrict__ fout, int mode) {
    extern __shared__ char smc[];
    uint32_t sb = s2u(smc);
    int tid = threadIdx.x, lane = tid & 31, warp = tid >> 5;
    int bi = blockIdx.z, n0 = blockIdx.x * 128;
    int wm = (warp >> 2) * 64, wn = (warp & 3) * 32;
    const char* Xb = (const char*)X + (size_t)bi * 4096 * 256;
    const char* Wb = (const char*)Wp;
    float acc[4][4][4] = {};
    const int NC = 36;
    auto stage = [&](int ch, int s) {
        int tap = ch >> 2, ci0 = (ch & 3) * 32;
        int ky = tap / 3 - 1, kx = tap % 3 - 1;
        for (int u = tid; u < 1024; u += 256) {
            int t = u >> 9, idx = u & 511, r = idx >> 2, c4 = idx & 3;
            uint32_t dst = sb + (s * 2 + t) * TILEB + r * RS + c4 * 16;
            if (t) {
                cp16(dst, Wb + (size_t)r * 2304 + (tap * 128 + ci0) * 2 + c4 * 16);
            } else {
                int p = n0 + r;
                int sy = (p >> 6) + ky, sx = (p & 63) + kx;
                bool ok = (unsigned)sy < 64u && (unsigned)sx < 64u;
                int sp = ok ? sy * 64 + sx : 0;
                cp16z(dst, Xb + (size_t)sp * 256 + ci0 * 2 + c4 * 16, ok);
            }
        }
    };
    stage(0, 0); CP_COMMIT;
    stage(1, 1); CP_COMMIT;
    stage(2, 2); CP_COMMIT;
    for (int i = 0; i < NC; i++) {
        CP_WAIT2;
        __syncthreads();
        if (i + 3 < NC) stage(i + 3, (i + 3) & 3);
        CP_COMMIT;
        uint32_t base = sb + (i & 3) * 2 * TILEB;
        mma_chunk1(base, base + TILEB, wm, wn, lane, acc);
    }
    if (mode == 0) {
        #pragma unroll
        for (int mi = 0; mi < 4; mi++)
            #pragma unroll
            for (int nj = 0; nj < 4; nj++) {
                int pr = wm + mi * 16 + (lane >> 2);
                int col = wn + nj * 8 + (lane & 3) * 2;
                float b0 = bias[col], b1 = bias[col + 1];
                float v0 = acc[mi][nj][0] + b0, v1 = acc[mi][nj][1] + b1;
                float v2 = acc[mi][nj][2] + b0, v3 = acc[mi][nj][3] + b1;
                v0 = v0 > 0.f ? v0 : (__expf(v0) - 1.0f);
                v1 = v1 > 0.f ? v1 : (__expf(v1) - 1.0f);
                v2 = v2 > 0.f ? v2 : (__expf(v2) - 1.0f);
                v3 = v3 > 0.f ? v3 : (__expf(v3) - 1.0f);
                __half2* o0 = (__half2*)&g_hT[((size_t)bi * 4096 + n0 + pr) * 128 + col];
                __half2* o1 = (__half2*)&g_hT[((size_t)bi * 4096 + n0 + pr + 8) * 128 + col];
                *o0 = __halves2half2(__float2half_rn(v0), __float2half_rn(v1));
                *o1 = __halves2half2(__float2half_rn(v2), __float2half_rn(v3));
            }
    } else {
        __syncthreads();
        float* sd = (float*)smc;
        #pragma unroll
        for (int mi = 0; mi < 4; mi++)
            #pragma unroll
            for (int nj = 0; nj < 4; nj++) {
                int pr = wm + mi * 16 + (lane >> 2);
                int col = wn + nj * 8 + (lane & 3) * 2;
                float b0 = bias[col], b1 = bias[col + 1];
                float v0 = acc[mi][nj][0] + b0, v1 = acc[mi][nj][1] + b1;
                float v2 = acc[mi][nj][2] + b0, v3 = acc[mi][nj][3] + b1;
                sd[pr * 129 + col] = v0 > 0.f ? v0 : (__expf(v0) - 1.0f);
                sd[pr * 129 + col + 1] = v1 > 0.f ? v1 : (__expf(v1) - 1.0f);
                sd[(pr + 8) * 129 + col] = v2 > 0.f ? v2 : (__expf(v2) - 1.0f);
                sd[(pr + 8) * 129 + col + 1] = v3 > 0.f ? v3 : (__expf(v3) - 1.0f);
            }
        __syncthreads();
        for (int u = tid; u < 16384; u += 256) {
            int pix = u & 127, co = u >> 7;
            fout[((size_t)bi * 128 + co) * 4096 + n0 + pix] = sd[pix * 129 + co];
        }
    }
}

// ---------------------------------------------------------------------------
extern "C" void kernel_launch(void* const* d_in, const int* in_sizes, int n_in,
                              void* d_out, int out_size) {
    const float* f  = (const float*)d_in[0];
    const float* b  = (const float*)d_in[1];
    const float* W1 = (const float*)d_in[2];
    const float* b1 = (const float*)d_in[3];
    const float* W2 = (const float*)d_in[4];
    const float* b2 = (const float*)d_in[5];
    float* out = (float*)d_out;

    cudaFuncSetAttribute(k_mmaG, cudaFuncAttributeMaxDynamicSharedMemorySize, 8 * TILEB);
    cudaFuncSetAttribute(k_mmaV, cudaFuncAttributeMaxDynamicSharedMemorySize, 8 * TILEB);
    cudaFuncSetAttribute(k_mmaConv, cudaFuncAttributeMaxDynamicSharedMemorySize, 82944);

    __half *yh, *hh, *w1p, *w2p;
    cudaGetSymbolAddress((void**)&yh, g_yT);
    cudaGetSymbolAddress((void**)&hh, g_hT);
    cudaGetSymbolAddress((void**)&w1p, g_W1p);
    cudaGetSymbolAddress((void**)&w2p, g_W2p);

    k_zero_sq<<<(BQ * LB + 255) / 256, 256>>>();
    k_pack_down<<<dim3(32, 4, BQ), 256>>>(f, b);
    k_norm2<<<BQ, 1024>>>();

    k_mmaG<<<dim3(8, 8, BQ), 256, 8 * TILEB>>>();
    k_mid<<<NB_ST + NB_BSH + NB_PW, 256>>>(b, W1, W2);
    k_fuse_smT<<<dim3(1024, BQ), 256>>>();

    k_mmaV<<<dim3(8, 16, BQ), 256, 8 * TILEB>>>();
    k_comb_pack<<<(int)(((size_t)BQ * 4096 * 64 + 255) / 256), 256>>>();

    k_mmaConv<<<dim3(32, 1, BQ), 256, 82944>>>(yh, w1p, b1, nullptr, 0);
    k_mmaConv<<<dim3(32, 1, BQ), 256, 82944>>>(hh, w2p, b2, out, 1);

    (void)in_sizes; (void)n_in; (void)out_size;
}

// round 17
// speedup vs baseline: 1.0762x; 1.0364x over previous
#include <cuda_runtime.h>
#include <cuda_fp16.h>
#include <cstdint>
#include <math.h>

#define BQ 16
#define CC 128
#define LB 1024
#define LF 1024
#define RS 80                   // smem row stride (bytes) — conflict-free ldmatrix
#define TILEB (128 * RS)        // 10240 bytes per 128x32-f16 tile

// ---------------- device scratch ----------------
__device__ float g_sq[BQ * LB];
__device__ float g_invn[BQ * LB];
__device__ float g_buf1[(size_t)BQ * LB * LF];   // GT
__device__ float g_buf2[(size_t)BQ * LB * LF];   // ST
__device__ __align__(16) __half g_Vh[(size_t)BQ * 16 * LF * CC];

__device__ __align__(16) __half g_bdT_h[(size_t)BQ * LB * CC];
__device__ __align__(16) __half g_bdT_l[(size_t)BQ * LB * CC];
__device__ __align__(16) __half g_fdT_h[(size_t)BQ * LB * CC];
__device__ __align__(16) __half g_fdT_l[(size_t)BQ * LB * CC];
__device__ __align__(16) __half g_bp[(size_t)BQ * 16 * CC * LB];
__device__ __align__(16) __half g_attT[(size_t)BQ * LF * LB];
__device__ __align__(16) __half g_yT[(size_t)BQ * 4096 * CC];
__device__ __align__(16) __half g_hT[(size_t)BQ * 4096 * CC];
__device__ __align__(16) __half g_W1p[CC * 1152];
__device__ __align__(16) __half g_W2p[CC * 1152];

// ---------------- asm helpers ----------------
__device__ __forceinline__ uint32_t s2u(const void* p) {
    uint32_t a;
    asm("{ .reg .u64 t; cvta.to.shared.u64 t, %1; cvt.u32.u64 %0, t; }" : "=r"(a) : "l"(p));
    return a;
}
__device__ __forceinline__ void cp16(uint32_t d, const void* s) {
    asm volatile("cp.async.cg.shared.global [%0], [%1], 16;" :: "r"(d), "l"(s));
}
__device__ __forceinline__ void cp16z(uint32_t d, const void* s, bool ok) {
    int sz = ok ? 16 : 0;
    asm volatile("cp.async.cg.shared.global [%0], [%1], 16, %2;" :: "r"(d), "l"(s), "r"(sz));
}
#define CP_COMMIT asm volatile("cp.async.commit_group;")
#define CP_WAIT1  asm volatile("cp.async.wait_group 1;")
#define CP_WAIT2  asm volatile("cp.async.wait_group 2;")

__device__ __forceinline__ void ldsm4(uint32_t* r, uint32_t a) {
    asm volatile("ldmatrix.sync.aligned.m8n8.x4.shared.b16 {%0,%1,%2,%3}, [%4];"
                 : "=r"(r[0]), "=r"(r[1]), "=r"(r[2]), "=r"(r[3]) : "r"(a));
}
__device__ __forceinline__ void mma16816(float* c, const uint32_t* a, const uint32_t* b) {
    asm volatile(
        "mma.sync.aligned.m16n8k16.row.col.f32.f16.f16.f32 "
        "{%0,%1,%2,%3}, {%4,%5,%6,%7}, {%8,%9}, {%0,%1,%2,%3};"
        : "+f"(c[0]), "+f"(c[1]), "+f"(c[2]), "+f"(c[3])
        : "r"(a[0]), "r"(a[1]), "r"(a[2]), "r"(a[3]), "r"(b[0]), "r"(b[1]));
}
__device__ __forceinline__ void split2h(float v, __half* ph, __half* pl) {
    __half h = __float2half_rn(v);
    *ph = h;
    *pl = __float2half_rn(v - __half2float(h));
}
__device__ __forceinline__ uint32_t a_addr(uint32_t tile, int m, int kk, int lane) {
    return tile + (m + (lane & 15)) * RS + (kk + ((lane >> 4) << 3)) * 2;
}
__device__ __forceinline__ uint32_t b_addr(uint32_t tile, int n, int kk, int lane) {
    return tile + (n + (lane & 7) + ((lane & 16) >> 1)) * RS + (kk + (lane & 8)) * 2;
}

__device__ __forceinline__ void mma_chunk1(uint32_t aT, uint32_t bT, int wm, int wn,
                                           int lane, float acc[4][4][4]) {
    #pragma unroll
    for (int kk = 0; kk < 32; kk += 16) {
        uint32_t a[4][4], bf[2][4];
        #pragma unroll
        for (int mi = 0; mi < 4; mi++) ldsm4(a[mi], a_addr(aT, wm + mi * 16, kk, lane));
        #pragma unroll
        for (int ni = 0; ni < 2; ni++) ldsm4(bf[ni], b_addr(bT, wn + ni * 16, kk, lane));
        #pragma unroll
        for (int mi = 0; mi < 4; mi++)
            #pragma unroll
            for (int nj = 0; nj < 4; nj++)
                mma16816(acc[mi][nj], a[mi], &bf[nj >> 1][(nj & 1) * 2]);
    }
}

__device__ __forceinline__ void mma_chunk3(uint32_t AhT, uint32_t AlT, uint32_t BhT,
                                           uint32_t BlT, int wm, int wn, int lane,
                                           float acc[4][4][4]) {
    #pragma unroll
    for (int kk = 0; kk < 32; kk += 16) {
        uint32_t ah[4][4], al[4][4], bh[2][4], bl[2][4];
        #pragma unroll
        for (int mi = 0; mi < 4; mi++) {
            ldsm4(ah[mi], a_addr(AhT, wm + mi * 16, kk, lane));
            ldsm4(al[mi], a_addr(AlT, wm + mi * 16, kk, lane));
        }
        #pragma unroll
        for (int ni = 0; ni < 2; ni++) {
            ldsm4(bh[ni], b_addr(BhT, wn + ni * 16, kk, lane));
            ldsm4(bl[ni], b_addr(BlT, wn + ni * 16, kk, lane));
        }
        #pragma unroll
        for (int mi = 0; mi < 4; mi++)
            #pragma unroll
            for (int nj = 0; nj < 4; nj++) {
                mma16816(acc[mi][nj], ah[mi], &bh[nj >> 1][(nj & 1) * 2]);
                mma16816(acc[mi][nj], ah[mi], &bl[nj >> 1][(nj & 1) * 2]);
                mma16816(acc[mi][nj], al[mi], &bh[nj >> 1][(nj & 1) * 2]);
            }
    }
}

// ---------------- pack / elementwise ----------------
__global__ void k_zero_sq() {
    int i = blockIdx.x * 256 + threadIdx.x;
    if (i < BQ * LB) g_sq[i] = 0.f;
}

// pack fd/bd -> [p][c] hi/lo via smem transpose; also accumulate bd sumsq per p
__global__ void k_pack_down(const float* __restrict__ f, const float* __restrict__ b) {
    __shared__ float tf[32][33], tb[32][33];
    int bi = blockIdx.z;
    int yb = blockIdx.x;
    int c0 = blockIdx.y * 32;
    int lane = threadIdx.x & 31, w = threadIdx.x >> 5;
    for (int yy = w; yy < 32; yy += 8) {
        size_t src = ((size_t)(bi * CC + c0 + yy) * 64 + 2 * yb) * 64 + 2 * lane;
        tf[yy][lane] = f[src];
        tb[yy][lane] = b[src];
    }
    __syncthreads();
    for (int yy = w; yy < 32; yy += 8) {
        float bv = tb[lane][yy];
        size_t o = ((size_t)(bi * 1024 + yb * 32 + yy)) * 128 + c0 + lane;
        split2h(tf[lane][yy], &g_fdT_h[o], &g_fdT_l[o]);
        split2h(bv, &g_bdT_h[o], &g_bdT_l[o]);
        float sq = bv * bv;
        #pragma unroll
        for (int off = 16; off; off >>= 1) sq += __shfl_xor_sync(0xFFFFFFFFu, sq, off);
        if (lane == 0) atomicAdd(&g_sq[bi * 1024 + yb * 32 + yy], sq);
    }
}

__global__ void k_norm2() {
    int bi = blockIdx.x, p = threadIdx.x;
    __shared__ float sq[LB];
    sq[p] = g_sq[bi * LB + p];
    __syncthreads();
    int y = p >> 5, x = p & 31;
    float ns = 0.f;
    #pragma unroll
    for (int dy = -1; dy <= 1; dy++)
        #pragma unroll
        for (int dx = -1; dx <= 1; dx++) {
            int y2 = y + dy, x2 = x + dx;
            if ((unsigned)y2 < 32u && (unsigned)x2 < 32u) ns += sq[(y2 << 5) + x2];
        }
    float n = sqrtf(ns); if (n < 1e-4f) n = 1e-4f;
    g_invn[bi * LB + p] = 1.0f / n;
}

// Merged mid kernel: ST stencil (diagonal-offset form, 4 outputs/thread),
// then bshift pack, then W pack.
#define NB_ST   16384
#define NB_BSH  2048
#define NB_PW   576
__global__ __launch_bounds__(256) void k_mid(const float* __restrict__ b,
                                             const float* __restrict__ W1,
                                             const float* __restrict__ W2) {
    __shared__ float sm[64][65];
    int x = blockIdx.x;
    int tid = threadIdx.x;
    if (x < NB_ST) {
        int bi = x >> 10;
        const float* GT = g_buf1 + ((size_t)bi << 20);
        float* OUT = g_buf2 + ((size_t)bi << 20);
        const float* INV = g_invn + bi * LB;
        int ibase = (x & 1023) * 1024 + tid;
        #pragma unroll
        for (int j = 0; j < 4; j++) {
            int i = ibase + j * 256;
            int pb = i & 1023, pf = i >> 10;
            int yb = pb >> 5, xb = pb & 31, yf = pf >> 5, xf = pf & 31;
            bool rm = (yb > 0) && (yf > 0);
            bool rp = (yb < 31) && (yf < 31);
            bool cm = (xb > 0) && (xf > 0);
            bool cp = (xb < 31) && (xf < 31);
            const float* base = GT + (size_t)pf * LB + pb;
            float s = base[0];
            if (cm) s += base[-1025];
            if (cp) s += base[1025];
            if (rm) {
                s += base[-32 * 1025];
                if (cm) s += base[-33 * 1025];
                if (cp) s += base[-31 * 1025];
            }
            if (rp) {
                s += base[32 * 1025];
                if (cm) s += base[31 * 1025];
                if (cp) s += base[33 * 1025];
            }
            OUT[i] = s * INV[pb];
        }
    } else if (x < NB_ST + NB_BSH) {
        int t = x - NB_ST;
        int c = t & 127, bi = t >> 7;
        const float* src = b + (size_t)(bi * CC + c) * 4096;
        #pragma unroll
        for (int i = 0; i < 16; i++) {
            int u = i * 256 + tid;
            sm[u >> 6][u & 63] = src[u];
        }
        __syncthreads();
        __half* outb = g_bp + ((size_t)(bi * 16) * CC + c) * 1024;
        #pragma unroll
        for (int it = 0; it < 8; it++) {
            int u = it * 256 + tid;
            int tap = u >> 7, g8 = u & 127;
            int yb = g8 >> 2, xb8 = g8 & 3;
            int py = tap >> 2, px = tap & 3;
            int row = 2 * yb + py - 1;
            bool rowok = (unsigned)row < 64u;
            int r = rowok ? row : 0;
            int col0 = 16 * xb8 + px - 1;
            __half h[8];
            #pragma unroll
            for (int j = 0; j < 8; j++) {
                int col = col0 + 2 * j;
                float v = (rowok && (unsigned)col < 64u) ? sm[r][col] : 0.f;
                h[j] = __float2half_rn(v);
            }
            *(uint4*)&outb[(size_t)tap * CC * 1024 + g8 * 8] = *(uint4*)h;
        }
    } else {
        int t = x - NB_ST - NB_BSH;
        int i = t * 256 + tid;
        if (i < CC * 1152) {
            int k = i % 1152, co = i / 1152;
            int tap = k >> 7, ci = k & 127;
            int src = (co * 128 + ci) * 9 + tap;
            g_W1p[i] = __float2half_rn(W1[src]);
            g_W2p[i] = __float2half_rn(W2[src]);
        }
    }
}

// fuse2(fuse1(S)) for one lf-row + row softmax -> attT[lf][:] half.
// r_j = tr(tr(lb)+j): lb+32j in the interior, wraparound selects at yb edges.
// c_j analogous (block-uniform). Inner k-shift = flat +-1025 with edge flags.
__global__ __launch_bounds__(256) void k_fuse_smT() {
    __shared__ float red[256];
    int bi = blockIdx.y, lf = blockIdx.x;
    int tid = threadIdx.x;
    const float* ST = g_buf2 + ((size_t)bi << 20);
    // block-uniform c_j (lf side); -1 = invalid
    int yf = lf >> 5, xf = lf & 31;
    int c0 = lf;
    int c1 = (yf < 31) ? (lf + 32) : ((xf < 31) ? (xf + 1) : -1);
    int cm1 = (yf > 0) ? (lf - 32) : ((xf > 0) ? (991 + xf) : -1);
    float v[4];
    float m = -1e30f;
    #pragma unroll
    for (int rI = 0; rI < 4; rI++) {
        int lb = rI * 256 + tid;
        int yb = lb >> 5, xb = lb & 31;
        int r0 = lb;
        int r1 = (yb < 31) ? (lb + 32) : ((xb < 31) ? (xb + 1) : -1);
        int rm1 = (yb > 0) ? (lb - 32) : ((xb > 0) ? (991 + xb) : -1);
        float s = 0.f;
        // j = -1
        if (rm1 >= 0 && cm1 >= 0) {
            const float* base = ST + (size_t)cm1 * LB + rm1;
            if (rm1 > 0 && cm1 > 0) s += base[-1025];
            s += base[0];
            if (rm1 < 1023 && cm1 < 1023) s += base[1025];
        }
        // j = 0
        {
            const float* base = ST + (size_t)c0 * LB + r0;
            if (r0 > 0 && c0 > 0) s += base[-1025];
            s += base[0];
            if (r0 < 1023 && c0 < 1023) s += base[1025];
        }
        // j = +1
        if (r1 >= 0 && c1 >= 0) {
            const float* base = ST + (size_t)c1 * LB + r1;
            if (r1 > 0 && c1 > 0) s += base[-1025];
            s += base[0];
            if (r1 < 1023 && c1 < 1023) s += base[1025];
        }
        v[rI] = 10.0f * s;
        m = fmaxf(m, v[rI]);
    }
    red[tid] = m;
    __syncthreads();
    for (int s2 = 128; s2; s2 >>= 1) {
        if (tid < s2) red[tid] = fmaxf(red[tid], red[tid + s2]);
        __syncthreads();
    }
    m = red[0];
    __syncthreads();
    float sum = 0.f;
    #pragma unroll
    for (int rI = 0; rI < 4; rI++) { v[rI] = __expf(v[rI] - m); sum += v[rI]; }
    red[tid] = sum;
    __syncthreads();
    for (int s2 = 128; s2; s2 >>= 1) {
        if (tid < s2) red[tid] += red[tid + s2];
        __syncthreads();
    }
    float inv = 1.0f / red[0];
    __half* O = g_attT + (size_t)(bi * LF + lf) * 1024;
    #pragma unroll
    for (int rI = 0; rI < 4; rI++) O[rI * 256 + tid] = __float2half_rn(v[rI] * inv);
}

// combine V(half) -> yT[pix][c] (half), 2 channels per thread
__global__ void k_comb_pack() {
    size_t i = (size_t)blockIdx.x * 256 + threadIdx.x;
    if (i >= (size_t)BQ * 4096 * 64) return;
    int c2 = (int)(i & 63) * 2;
    int pix = (int)(i >> 6) & 4095;
    int bi = (int)(i >> 18);
    int oy = pix >> 6, ox = pix & 63;
    int my = oy >> 1, mx = ox >> 1;
    int yfv[2], pyv[2], xfv[2], pxv[2];
    if (oy & 1) { yfv[0] = my; pyv[0] = 2; yfv[1] = my + 1; pyv[1] = 0; }
    else        { yfv[0] = my; pyv[0] = 1; yfv[1] = my - 1; pyv[1] = 3; }
    if (ox & 1) { xfv[0] = mx; pxv[0] = 2; xfv[1] = mx + 1; pxv[1] = 0; }
    else        { xfv[0] = mx; pxv[0] = 1; xfv[1] = mx - 1; pxv[1] = 3; }
    float s0 = 0.f, s1 = 0.f;
    #pragma unroll
    for (int a = 0; a < 2; a++) {
        if ((unsigned)yfv[a] >= 32u) continue;
        #pragma unroll
        for (int b2 = 0; b2 < 2; b2++) {
            if ((unsigned)xfv[b2] >= 32u) continue;
            int tap = pyv[a] * 4 + pxv[b2];
            int lf = yfv[a] * 32 + xfv[b2];
            __half2 hv = *(const __half2*)&g_Vh[((size_t)(bi * 16 + tap) * LF + lf) * CC + c2];
            float2 fv = __half22float2(hv);
            s0 += fv.x; s1 += fv.y;
        }
    }
    *(__half2*)&g_yT[((size_t)bi * 4096 + pix) * CC + c2] =
        __halves2half2(__float2half_rn(0.25f * s0), __float2half_rn(0.25f * s1));
}

// ---------------- mma GEMM kernels ----------------
// GT = fdT(split) @ bdT(split)^T, K=128 (4 chunks, 3-pass), 2-stage, 2 blocks/SM
__global__ __launch_bounds__(256, 2) void k_mmaG() {
    extern __shared__ char smc[];
    uint32_t sb = s2u(smc);
    int tid = threadIdx.x, lane = tid & 31, warp = tid >> 5;
    int bi = blockIdx.z, m0 = blockIdx.y * 128, n0 = blockIdx.x * 128;
    int wm = (warp >> 2) * 64, wn = (warp & 3) * 32;
    const char* srcs[4] = {
        (const char*)g_fdT_h + (size_t)(bi * LB + m0) * 256,
        (const char*)g_fdT_l + (size_t)(bi * LB + m0) * 256,
        (const char*)g_bdT_h + (size_t)(bi * LB + n0) * 256,
        (const char*)g_bdT_l + (size_t)(bi * LB + n0) * 256};
    float acc[4][4][4] = {};
    auto stage = [&](int ch, int s) {
        for (int u = tid; u < 2048; u += 256) {
            int t = u >> 9, idx = u & 511, r = idx >> 2, c4 = idx & 3;
            cp16(sb + (s * 4 + t) * TILEB + r * RS + c4 * 16,
                 srcs[t] + (size_t)r * 256 + ch * 64 + c4 * 16);
        }
    };
    stage(0, 0); CP_COMMIT;
    for (int i = 0; i < 4; i++) {
        if (i + 1 < 4) { stage(i + 1, (i + 1) & 1); CP_COMMIT; CP_WAIT1; }
        else { asm volatile("cp.async.wait_group 0;"); }
        __syncthreads();
        uint32_t base = sb + (i & 1) * 4 * TILEB;
        mma_chunk3(base, base + TILEB, base + 2 * TILEB, base + 3 * TILEB, wm, wn, lane, acc);
        __syncthreads();
    }
    float* out = g_buf1 + ((size_t)bi << 20);
    #pragma unroll
    for (int mi = 0; mi < 4; mi++)
        #pragma unroll
        for (int nj = 0; nj < 4; nj++) {
            int grow = m0 + wm + mi * 16 + (lane >> 2);
            int gcol = n0 + wn + nj * 8 + (lane & 3) * 2;
            *(float2*)&out[(size_t)grow * LB + gcol] = make_float2(acc[mi][nj][0], acc[mi][nj][1]);
            *(float2*)&out[(size_t)(grow + 8) * LB + gcol] = make_float2(acc[mi][nj][2], acc[mi][nj][3]);
        }
}

// V[tap][lf][c] = attT.bp, M=128, K=1024 (32 chunks, 4-stage), 2 blocks/SM
__global__ __launch_bounds__(256, 2) void k_mmaV() {
    extern __shared__ char smc[];
    uint32_t sb = s2u(smc);
    int tid = threadIdx.x, lane = tid & 31, warp = tid >> 5;
    int bi = blockIdx.z, tap = blockIdx.y, m0 = blockIdx.x * 128;
    int wm = (warp >> 2) * 64, wn = (warp & 3) * 32;
    const char* srcA = (const char*)g_attT + (size_t)(bi * LF + m0) * 2048;
    const char* srcB = (const char*)g_bp + (size_t)((bi * 16 + tap) * CC) * 2048;
    float acc[4][4][4] = {};
    const int NC = 32;
    auto stage = [&](int ch, int s) {
        for (int u = tid; u < 1024; u += 256) {
            int t = u >> 9, idx = u & 511, r = idx >> 2, c4 = idx & 3;
            cp16(sb + (s * 2 + t) * TILEB + r * RS + c4 * 16,
                 (t ? srcB : srcA) + (size_t)r * 2048 + ch * 64 + c4 * 16);
        }
    };
    stage(0, 0); CP_COMMIT;
    stage(1, 1); CP_COMMIT;
    stage(2, 2); CP_COMMIT;
    for (int i = 0; i < NC; i++) {
        CP_WAIT2;
        __syncthreads();
        if (i + 3 < NC) stage(i + 3, (i + 3) & 3);
        CP_COMMIT;
        uint32_t base = sb + (i & 3) * 2 * TILEB;
        mma_chunk1(base, base + TILEB, wm, wn, lane, acc);
    }
    __half* out = g_Vh + (size_t)(bi * 16 + tap) * LF * CC;
    #pragma unroll
    for (int mi = 0; mi < 4; mi++)
        #pragma unroll
        for (int nj = 0; nj < 4; nj++) {
            int glf = m0 + wm + mi * 16 + (lane >> 2);
            int gc = wn + nj * 8 + (lane & 3) * 2;
            *(__half2*)&out[(size_t)glf * CC + gc] =
                __halves2half2(__float2half_rn(acc[mi][nj][0]), __float2half_rn(acc[mi][nj][1]));
            *(__half2*)&out[(size_t)(glf + 8) * CC + gc] =
                __halves2half2(__float2half_rn(acc[mi][nj][2]), __float2half_rn(acc[mi][nj][3]));
        }
}

// conv3x3 implicit GEMM: K=1152 (36 chunks, 4-stage), 2 blocks/SM
__global__ __launch_bounds__(256, 2) void k_mmaConv(
    const __half* __restrict__ X, const __half* __restrict__ Wp,
    const float* __restrict__ bias, float* __restrict__ fout, int mode) {
    extern __shared__ char smc[];
    uint32_t sb = s2u(smc);
    int tid = threadIdx.x, lane = tid & 31, warp = tid >> 5;
    int bi = blockIdx.z, n0 = blockIdx.x * 128;
    int wm = (warp >> 2) * 64, wn = (warp & 3) * 32;
    const char* Xb = (const char*)X + (size_t)bi * 4096 * 256;
    const char* Wb = (const char*)Wp;
    float acc[4][4][4] = {};
    const int NC = 36;
    auto stage = [&](int ch, int s) {
        int tap = ch >> 2, ci0 = (ch & 3) * 32;
        int ky = tap / 3 - 1, kx = tap % 3 - 1;
        for (int u = tid; u < 1024; u += 256) {
            int t = u >> 9, idx = u & 511, r = idx >> 2, c4 = idx & 3;
            uint32_t dst = sb + (s * 2 + t) * TILEB + r * RS + c4 * 16;
            if (t) {
                cp16(dst, Wb + (size_t)r * 2304 + (tap * 128 + ci0) * 2 + c4 * 16);
            } else {
                int p = n0 + r;
                int sy = (p >> 6) + ky, sx = (p & 63) + kx;
                bool ok = (unsigned)sy < 64u && (unsigned)sx < 64u;
                int sp = ok ? sy * 64 + sx : 0;
                cp16z(dst, Xb + (size_t)sp * 256 + ci0 * 2 + c4 * 16, ok);
            }
        }
    };
    stage(0, 0); CP_COMMIT;
    stage(1, 1); CP_COMMIT;
    stage(2, 2); CP_COMMIT;
    for (int i = 0; i < NC; i++) {
        CP_WAIT2;
        __syncthreads();
        if (i + 3 < NC) stage(i + 3, (i + 3) & 3);
        CP_COMMIT;
        uint32_t base = sb + (i & 3) * 2 * TILEB;
        mma_chunk1(base, base + TILEB, wm, wn, lane, acc);
    }
    if (mode == 0) {
        #pragma unroll
        for (int mi = 0; mi < 4; mi++)
            #pragma unroll
            for (int nj = 0; nj < 4; nj++) {
                int pr = wm + mi * 16 + (lane >> 2);
                int col = wn + nj * 8 + (lane & 3) * 2;
                float b0 = bias[col], b1 = bias[col + 1];
                float v0 = acc[mi][nj][0] + b0, v1 = acc[mi][nj][1] + b1;
                float v2 = acc[mi][nj][2] + b0, v3 = acc[mi][nj][3] + b1;
                v0 = v0 > 0.f ? v0 : (__expf(v0) - 1.0f);
                v1 = v1 > 0.f ? v1 : (__expf(v1) - 1.0f);
                v2 = v2 > 0.f ? v2 : (__expf(v2) - 1.0f);
                v3 = v3 > 0.f ? v3 : (__expf(v3) - 1.0f);
                __half2* o0 = (__half2*)&g_hT[((size_t)bi * 4096 + n0 + pr) * 128 + col];
                __half2* o1 = (__half2*)&g_hT[((size_t)bi * 4096 + n0 + pr + 8) * 128 + col];
                *o0 = __halves2half2(__float2half_rn(v0), __float2half_rn(v1));
                *o1 = __halves2half2(__float2half_rn(v2), __float2half_rn(v3));
            }
    } else {
        __syncthreads();
        float* sd = (float*)smc;
        #pragma unroll
        for (int mi = 0; mi < 4; mi++)
            #pragma unroll
            for (int nj = 0; nj < 4; nj++) {
                int pr = wm + mi * 16 + (lane >> 2);
                int col = wn + nj * 8 + (lane & 3) * 2;
                float b0 = bias[col], b1 = bias[col + 1];
                float v0 = acc[mi][nj][0] + b0, v1 = acc[mi][nj][1] + b1;
                float v2 = acc[mi][nj][2] + b0, v3 = acc[mi][nj][3] + b1;
                sd[pr * 129 + col] = v0 > 0.f ? v0 : (__expf(v0) - 1.0f);
                sd[pr * 129 + col + 1] = v1 > 0.f ? v1 : (__expf(v1) - 1.0f);
                sd[(pr + 8) * 129 + col] = v2 > 0.f ? v2 : (__expf(v2) - 1.0f);
                sd[(pr + 8) * 129 + col + 1] = v3 > 0.f ? v3 : (__expf(v3) - 1.0f);
            }
        __syncthreads();
        for (int u = tid; u < 16384; u += 256) {
            int pix = u & 127, co = u >> 7;
            fout[((size_t)bi * 128 + co) * 4096 + n0 + pix] = sd[pix * 129 + co];
        }
    }
}

// ---------------------------------------------------------------------------
extern "C" void kernel_launch(void* const* d_in, const int* in_sizes, int n_in,
                              void* d_out, int out_size) {
    const float* f  = (const float*)d_in[0];
    const float* b  = (const float*)d_in[1];
    const float* W1 = (const float*)d_in[2];
    const float* b1 = (const float*)d_in[3];
    const float* W2 = (const float*)d_in[4];
    const float* b2 = (const float*)d_in[5];
    float* out = (float*)d_out;

    cudaFuncSetAttribute(k_mmaG, cudaFuncAttributeMaxDynamicSharedMemorySize, 8 * TILEB);
    cudaFuncSetAttribute(k_mmaV, cudaFuncAttributeMaxDynamicSharedMemorySize, 8 * TILEB);
    cudaFuncSetAttribute(k_mmaConv, cudaFuncAttributeMaxDynamicSharedMemorySize, 82944);

    __half *yh, *hh, *w1p, *w2p;
    cudaGetSymbolAddress((void**)&yh, g_yT);
    cudaGetSymbolAddress((void**)&hh, g_hT);
    cudaGetSymbolAddress((void**)&w1p, g_W1p);
    cudaGetSymbolAddress((void**)&w2p, g_W2p);

    k_zero_sq<<<(BQ * LB + 255) / 256, 256>>>();
    k_pack_down<<<dim3(32, 4, BQ), 256>>>(f, b);
    k_norm2<<<BQ, 1024>>>();

    k_mmaG<<<dim3(8, 8, BQ), 256, 8 * TILEB>>>();
    k_mid<<<NB_ST + NB_BSH + NB_PW, 256>>>(b, W1, W2);
    k_fuse_smT<<<dim3(1024, BQ), 256>>>();

    k_mmaV<<<dim3(8, 16, BQ), 256, 8 * TILEB>>>();
    k_comb_pack<<<(int)(((size_t)BQ * 4096 * 64 + 255) / 256), 256>>>();

    k_mmaConv<<<dim3(32, 1, BQ), 256, 82944>>>(yh, w1p, b1, nullptr, 0);
    k_mmaConv<<<dim3(32, 1, BQ), 256, 82944>>>(hh, w2p, b2, out, 1);

    (void)in_sizes; (void)n_in; (void)out_size;
}